// round 3
// baseline (speedup 1.0000x reference)
#include <cuda_runtime.h>
#include <cuda_fp16.h>
#include <cstdint>

#define TOKENS   64
#define NFEAT    8192
#define KFEAT    8192            // codes per row
#define KHALF    (KFEAT * 2)     // fp16 k after 2x inflation

#define KSPLIT    4
#define KC_CODES  (KFEAT / KSPLIT)       // 2048 codes per CTA
#define CTA_N     128
#define ITER_C    32                      // codes per mainloop iter (= 64 halves)
#define NITER     (KC_CODES / ITER_C)     // 64
#define PITCH     72                      // halves per smem A row (144B, conflict-free)

// scratch
__device__ __align__(16) __half g_xe[TOKENS * KHALF];             // 2 MB expanded/permuted x
__device__ float g_sumx[TOKENS];
__device__ __align__(16) float g_part[KSPLIT][TOKENS * NFEAT];    // 8 MB

// ---------------------------------------------------------------------------
// Prep: x fp32 -> fp16, permuted 2x-expanded layout; per-token sum of x16.
// For 16-code group: code j -> uint32 word w=(j&3)*4+(j>>2), lo=x16, hi=0.
// ---------------------------------------------------------------------------
__global__ __launch_bounds__(256) void prep_kernel(const float* __restrict__ x) {
    __shared__ float red[256];
    const int t = blockIdx.x, tid = threadIdx.x;
    const float* xr = x + (size_t)t * KFEAT;
    uint32_t* dst = reinterpret_cast<uint32_t*>(g_xe + (size_t)t * KHALF);
    float sm = 0.f;
#pragma unroll
    for (int gi = 0; gi < 2; gi++) {
        int g = tid + gi * 256;                 // group of 16 codes
        float4 v[4];
#pragma unroll
        for (int i = 0; i < 4; i++) v[i] = reinterpret_cast<const float4*>(xr + g * 16)[i];
        uint32_t w[16];
#pragma unroll
        for (int j = 0; j < 16; j++) {
            float f = ((const float*)v)[j];
            __half h = __float2half_rn(f);
            sm += __half2float(h);
            w[(j & 3) * 4 + (j >> 2)] = (uint32_t)__half_as_ushort(h);
        }
#pragma unroll
        for (int i = 0; i < 4; i++)
            reinterpret_cast<uint4*>(dst + g * 16)[i] =
                make_uint4(w[i * 4 + 0], w[i * 4 + 1], w[i * 4 + 2], w[i * 4 + 3]);
    }
    red[tid] = sm; __syncthreads();
    for (int s = 128; s > 0; s >>= 1) { if (tid < s) red[tid] += red[tid + s]; __syncthreads(); }
    if (tid == 0) g_sumx[t] = red[0];
}

// ---------------------------------------------------------------------------
__device__ __forceinline__ void cpa16(uint32_t dst, const void* src) {
    asm volatile("cp.async.ca.shared.global [%0], [%1], 16;\n" :: "r"(dst), "l"(src));
}
__device__ __forceinline__ void mma16816(float* d, const uint32_t* a, uint32_t b0, uint32_t b1) {
    asm volatile(
        "mma.sync.aligned.m16n8k16.row.col.f32.f16.f16.f32 "
        "{%0,%1,%2,%3},{%4,%5,%6,%7},{%8,%9},{%0,%1,%2,%3};"
        : "+f"(d[0]), "+f"(d[1]), "+f"(d[2]), "+f"(d[3])
        : "r"(a[0]), "r"(a[1]), "r"(a[2]), "r"(a[3]), "r"(b0), "r"(b1));
}

// ---------------------------------------------------------------------------
// GEMM: raw weight words fed straight into HMMA as fp16 subnormals.
// acc = sum_k x16 * c * 2^-24 ; stored raw to g_part.
// ---------------------------------------------------------------------------
__global__ __launch_bounds__(256, 2) void gemm_kernel(const int* __restrict__ q) {
    __shared__ __align__(16) __half sA[2][TOKENS * PITCH];   // 2 x 9216 B

    const int tid  = threadIdx.x;
    const int warp = tid >> 5;
    const int lane = tid & 31;

    const int n0 = blockIdx.x * CTA_N + warp * 16;
    const int kbc = blockIdx.y * KC_CODES;            // code base
    const int kbh = kbc * 2;                           // half base

    const int r0 = n0 + (lane >> 2);
    const int r1 = r0 + 8;
    const int c4 = (lane & 3) * 4;                     // int4 code offset within group

    const int* pB0 = q + (size_t)r0 * KFEAT + kbc + c4;
    const int* pB1 = q + (size_t)r1 * KFEAT + kbc + c4;

    // A staging: 64 rows x 64 halves (128B) per chunk; 256 thr -> 32B each
    const int arow = tid >> 2;
    const int aseg = tid & 3;
    const __half* asrc = g_xe + (size_t)arow * KHALF + kbh + aseg * 16;
    const uint32_t sbase = (uint32_t)__cvta_generic_to_shared(&sA[0][0]);
    const uint32_t BUFB  = TOKENS * PITCH * 2;
    const uint32_t adst  = (uint32_t)(arow * PITCH * 2 + aseg * 32);

    // prologue
    cpa16(sbase + adst, asrc);
    cpa16(sbase + adst + 16, asrc + 8);
    asm volatile("cp.async.commit_group;\n");

    int4 raw[2][2];   // [nf][g2]
#pragma unroll
    for (int g2 = 0; g2 < 2; g2++) {
        raw[0][g2] = __ldcs((const int4*)(pB0 + g2 * 16));
        raw[1][g2] = __ldcs((const int4*)(pB1 + g2 * 16));
    }

    float acc[4][2][4];
#pragma unroll
    for (int mi = 0; mi < 4; mi++)
#pragma unroll
        for (int nf = 0; nf < 2; nf++)
#pragma unroll
            for (int j = 0; j < 4; j++) acc[mi][nf][j] = 0.f;

    int buf = 0;
    for (int c = 0; c < NITER; ++c) {
        asm volatile("cp.async.wait_group 0;\n" ::: "memory");
        __syncthreads();

        if (c + 1 < NITER) {
            const __half* s2 = asrc + (size_t)(c + 1) * ITER_C * 2;
            cpa16(sbase + (buf ^ 1) * BUFB + adst, s2);
            cpa16(sbase + (buf ^ 1) * BUFB + adst + 16, s2 + 8);
            asm volatile("cp.async.commit_group;\n");
        }

        int4 cur[2][2];
#pragma unroll
        for (int nf = 0; nf < 2; nf++)
#pragma unroll
            for (int g2 = 0; g2 < 2; g2++) cur[nf][g2] = raw[nf][g2];

        if (c + 1 < NITER) {
            const int off = (c + 1) * ITER_C;
#pragma unroll
            for (int g2 = 0; g2 < 2; g2++) {
                raw[0][g2] = __ldcs((const int4*)(pB0 + off + g2 * 16));
                raw[1][g2] = __ldcs((const int4*)(pB1 + off + g2 * 16));
            }
        }

        const uint32_t abase = sbase + buf * BUFB;
        const int rl = lane & 15;
        const int kh = (lane >> 4) * 8;
#pragma unroll
        for (int g2 = 0; g2 < 2; g2++) {
#pragma unroll
            for (int s = 0; s < 2; s++) {
                uint32_t a[4][4];
#pragma unroll
                for (int mi = 0; mi < 4; mi++) {
                    uint32_t addr = abase +
                        (uint32_t)((mi * 16 + rl) * PITCH + g2 * 32 + s * 16 + kh) * 2;
                    asm volatile(
                        "ldmatrix.sync.aligned.m8n8.x4.shared.b16 {%0,%1,%2,%3}, [%4];"
                        : "=r"(a[mi][0]), "=r"(a[mi][1]), "=r"(a[mi][2]), "=r"(a[mi][3])
                        : "r"(addr));
                }
#pragma unroll
                for (int nf = 0; nf < 2; nf++) {
                    uint32_t b0 = s == 0 ? (uint32_t)cur[nf][g2].x : (uint32_t)cur[nf][g2].z;
                    uint32_t b1 = s == 0 ? (uint32_t)cur[nf][g2].y : (uint32_t)cur[nf][g2].w;
#pragma unroll
                    for (int mi = 0; mi < 4; mi++)
                        mma16816(acc[mi][nf], a[mi], b0, b1);
                }
            }
        }
        buf ^= 1;
    }

    float* pp = &g_part[blockIdx.y][0];
    const int kc2 = (lane & 3) * 2;
#pragma unroll
    for (int mi = 0; mi < 4; mi++)
#pragma unroll
        for (int nf = 0; nf < 2; nf++) {
            int col = n0 + nf * 8 + kc2;
            int t0  = mi * 16 + (lane >> 2);
            *reinterpret_cast<float2*>(&pp[(size_t)t0 * NFEAT + col]) =
                make_float2(acc[mi][nf][0], acc[mi][nf][1]);
            *reinterpret_cast<float2*>(&pp[(size_t)(t0 + 8) * NFEAT + col]) =
                make_float2(acc[mi][nf][2], acc[mi][nf][3]);
        }
}

// ---------------------------------------------------------------------------
// Reduce: y = s * (2^24 * sum_parts - zp * sumx_t) + bias
// ---------------------------------------------------------------------------
__global__ void reduce_kernel(const float* __restrict__ scales,
                              const int* __restrict__ zp,
                              const float* __restrict__ bias,
                              float* __restrict__ out) {
    int i = blockIdx.x * blockDim.x + threadIdx.x;     // float4 units
    int col4 = i & (NFEAT / 4 - 1);
    int t    = i >> 11;
    float4 a = reinterpret_cast<const float4*>(g_part[0])[i];
    float4 b = reinterpret_cast<const float4*>(g_part[1])[i];
    float4 c = reinterpret_cast<const float4*>(g_part[2])[i];
    float4 d = reinterpret_cast<const float4*>(g_part[3])[i];
    float4 sc = reinterpret_cast<const float4*>(scales)[col4];
    float4 bi = reinterpret_cast<const float4*>(bias)[col4];
    int4   zi = reinterpret_cast<const int4*>(zp)[col4];
    float sx = g_sumx[t];
    const float SC = 16777216.0f;  // 2^24
    float4 r;
    r.x = bi.x + sc.x * (SC * (a.x + b.x + c.x + d.x) - (float)zi.x * sx);
    r.y = bi.y + sc.y * (SC * (a.y + b.y + c.y + d.y) - (float)zi.y * sx);
    r.z = bi.z + sc.z * (SC * (a.z + b.z + c.z + d.z) - (float)zi.z * sx);
    r.w = bi.w + sc.w * (SC * (a.w + b.w + c.w + d.w) - (float)zi.w * sx);
    reinterpret_cast<float4*>(out)[i] = r;
}

// ---------------------------------------------------------------------------
extern "C" void kernel_launch(void* const* d_in, const int* in_sizes, int n_in,
                              void* d_out, int out_size) {
    const float* x    = (const float*)d_in[0];
    const int*   qw   = (const int*)d_in[1];
    const float* sc   = (const float*)d_in[2];
    const int*   zp   = (const int*)d_in[3];
    const float* bias = (const float*)d_in[4];
    float*       out  = (float*)d_out;
    (void)in_sizes; (void)n_in; (void)out_size;

    prep_kernel<<<TOKENS, 256>>>(x);
    gemm_kernel<<<dim3(NFEAT / CTA_N, KSPLIT), 256>>>(qw);
    reduce_kernel<<<(TOKENS * NFEAT / 4) / 256, 256>>>(sc, zp, bias, out);
}